// round 5
// baseline (speedup 1.0000x reference)
#include <cuda_runtime.h>
#include <math.h>

#define HH 56
#define WW 56
#define NB 256
#define BATCH 8
#define CHANNELS 1024
#define PLANE (HH*WW)           // 3136
#define BC (BATCH*CHANNELS)     // 8192
#define NELEM (BC*PLANE)        // 25,690,112
#define N4 (NELEM/4)            // 6,422,528 float4
#define T_THRESH 0.9f

#define HIST_BLOCKS 592
#define HIST_THREADS 512

// ------------------------- device scratch (no allocations) -------------------
__device__ unsigned int g_total[NB];          // zeroed by k_decide each replay
__device__ unsigned int g_col0[WW*NB];        // zeroed by k_decide each replay
__device__ unsigned int g_cell[HH*WW*NB];     // heavy path scratch (12.8MB)
__device__ unsigned int g_bar;                // heavy path grid barrier
__device__ int   g_region[4];                 // xs, xd, ys, yd
__device__ int   g_flag;                      // 1 => heavy path needed
__device__ float g_total_ent;
__device__ int   g_ys0;

// ------------------------- helpers ------------------------------------------
__device__ __forceinline__ float blockReduceSum(float v) {
    __shared__ float s_red[32];
    unsigned lane = threadIdx.x & 31u;
    unsigned wid  = threadIdx.x >> 5;
    #pragma unroll
    for (int o = 16; o; o >>= 1) v += __shfl_xor_sync(0xffffffffu, v, o);
    if (lane == 0) s_red[wid] = v;
    __syncthreads();
    unsigned nw = (blockDim.x + 31u) >> 5;
    if (wid == 0) {
        float t = (lane < nw) ? s_red[lane] : 0.0f;
        #pragma unroll
        for (int o = 16; o; o >>= 1) t += __shfl_xor_sync(0xffffffffu, t, o);
        if (lane == 0) s_red[0] = t;
    }
    __syncthreads();
    float r = s_red[0];
    __syncthreads();
    return r;
}

__device__ __forceinline__ float warpReduceSum(float v) {
    #pragma unroll
    for (int o = 16; o; o >>= 1) v += __shfl_xor_sync(0xffffffffu, v, o);
    return v;
}

__device__ __forceinline__ int bin_of(float v) {   // caller guarantees v >= 0
    int b = (int)(v * 256.0f);
    return b > 255 ? 255 : b;
}

// ------------------------- k1: fused total + column-0 histograms -------------
__device__ __forceinline__ void hist_one(unsigned int* h, float4 v, int i) {
    int b0 = bin_of(v.x), b1 = bin_of(v.y), b2 = bin_of(v.z), b3 = bin_of(v.w);
    bool v0 = (v.x >= 0.0f && v.x <= 1.0f);
    bool v1 = (v.y >= 0.0f && v.y <= 1.0f);
    bool v2 = (v.z >= 0.0f && v.z <= 1.0f);
    bool v3 = (v.w >= 0.0f && v.w <= 1.0f);
    if (v0) atomicAdd(&h[b0], 1u);
    if (v1) atomicAdd(&h[b1], 1u);
    if (v2) atomicAdd(&h[b2], 1u);
    if (v3) atomicAdd(&h[b3], 1u);
    int m = i % 784;                 // h==0 iff (i % 784) < 14
    if (m < 14) {
        int w = 4 * m;
        if (v0) atomicAdd(&g_col0[(w + 0) * NB + b0], 1u);
        if (v1) atomicAdd(&g_col0[(w + 1) * NB + b1], 1u);
        if (v2) atomicAdd(&g_col0[(w + 2) * NB + b2], 1u);
        if (v3) atomicAdd(&g_col0[(w + 3) * NB + b3], 1u);
    }
}

__global__ void __launch_bounds__(HIST_THREADS) k_hist(const float4* __restrict__ x4) {
    __shared__ unsigned int sh[16 * NB];   // per-warp replicas, 16KB
    for (int i = threadIdx.x; i < 16 * NB; i += blockDim.x) sh[i] = 0u;
    __syncthreads();
    unsigned int* h = sh + (threadIdx.x >> 5) * NB;
    const int stride = HIST_BLOCKS * HIST_THREADS;
    int i = blockIdx.x * HIST_THREADS + threadIdx.x;
    // 2-wide unrolled grid-stride for load MLP
    for (; i + stride < N4; i += 2 * stride) {
        float4 a = x4[i];
        float4 b = x4[i + stride];
        hist_one(h, a, i);
        hist_one(h, b, i + stride);
    }
    if (i < N4) hist_one(h, x4[i], i);
    __syncthreads();
    if (threadIdx.x < NB) {
        unsigned int s = 0;
        #pragma unroll
        for (int r = 0; r < 16; r++) s += sh[r * NB + threadIdx.x];
        atomicAdd(&g_total[threadIdx.x], s);
    }
}

// ------------------------- k2: decide (entropies + argmax + flag) ------------
__global__ void k_decide() {   // 1 block, 256 threads
    int tid = threadIdx.x;
    int lane = tid & 31, wrp = tid >> 5;

    // total entropy (tid == bin)
    float c = (float)g_total[tid];
    float s = blockReduceSum(c);
    float p = c / s;
    float tot = -blockReduceSum(p * log2f(p + 1e-9f));

    // per-column entropies: warp per column
    __shared__ float s_ent[WW];
    for (int w = wrp; w < WW; w += 8) {
        float cs = 0.0f;
        float cc[8];
        #pragma unroll
        for (int k = 0; k < 8; k++) {
            cc[k] = (float)g_col0[w * NB + lane + k * 32];
            cs += cc[k];
        }
        cs = warpReduceSum(cs);
        float e = 0.0f;
        #pragma unroll
        for (int k = 0; k < 8; k++) {
            float pp = cc[k] / cs;
            e += pp * log2f(pp + 1e-9f);
        }
        e = -warpReduceSum(e);
        if (lane == 0) s_ent[w] = e;
    }
    __syncthreads();
    if (tid == 0) {
        float bestEnt = -1e30f; int bestw = 0;
        for (int w = 0; w < WW; w++)
            if (s_ent[w] > bestEnt) { bestEnt = s_ent[w]; bestw = w; }
        float Ts0 = bestEnt / tot;
        if (Ts0 < T_THRESH) {
            g_flag = 1;
            g_ys0 = bestw;
            g_total_ent = tot;
        } else {
            g_flag = 0;
            g_region[0] = 0; g_region[1] = 1;
            g_region[2] = bestw; g_region[3] = bestw + 1;
        }
    }
    __syncthreads();
    // re-zero accumulators for the next graph replay
    g_total[tid] = 0u;
    for (int j = tid; j < WW * NB; j += 256) g_col0[j] = 0u;
}

// ------------------------- k3: heavy path, ONE kernel (flag-gated) -----------
__device__ __forceinline__ float integA(int i, int j, int tid) {
    if (i <= 0 || j <= 0) return 0.0f;
    return (float)g_cell[((size_t)((i - 1) * WW + (j - 1))) * NB + tid];
}

__device__ float region_ent(int xd, int ys, int yd, int tid) {
    float a = integA(xd, yd, tid) - integA(xd, ys, tid);
    float s = blockReduceSum(a);
    float p = a / s;
    return -blockReduceSum(p * log2f(p + 1e-9f));
}

// 112 blocks (single wave, all resident), 256 threads, 28KB smem
__global__ void __launch_bounds__(256) k_heavy(const float* __restrict__ x) {
    if (!g_flag) return;
    __shared__ unsigned int sh[28 * NB];   // 28KB; phase2 reuses first 12.5KB
    int tid = threadIdx.x;

    // ---- phase 1: per-(h,w)-cell histograms (block owns 28 cells) ----
    for (int i = tid; i < 28 * NB; i += blockDim.x) sh[i] = 0u;
    __syncthreads();
    int h     = blockIdx.x >> 1;
    int whalf = blockIdx.x & 1;
    const int TOT = BC * 28;
    for (int i = tid; i < TOT; i += blockDim.x) {
        int bc   = i / 28;
        int wloc = i % 28;
        float v = x[(size_t)bc * PLANE + h * WW + whalf * 28 + wloc];
        if (v >= 0.0f && v <= 1.0f)
            atomicAdd(&sh[wloc * NB + bin_of(v)], 1u);
    }
    __syncthreads();
    for (int i = tid; i < 28 * NB; i += blockDim.x)
        g_cell[((size_t)(h * WW + whalf * 28 + (i >> 8))) * NB + (i & 255)] = sh[i];

    // ---- grid barrier 1 (all 112 blocks resident: single wave) ----
    __threadfence();
    __syncthreads();
    if (tid == 0) atomicAdd(&g_bar, 1u);
    if (tid == 0) { while (atomicAdd(&g_bar, 0u) < 112u) { } }
    __syncthreads();
    __threadfence();

    // ---- phase 2: 2D integral per bin ----
    unsigned int* s = sh;   // reuse: HH*WW = 3136 words
    for (int bin = blockIdx.x; bin < NB; bin += gridDim.x) {
        for (int i = tid; i < HH * WW; i += blockDim.x)
            s[i] = g_cell[(size_t)i * NB + bin];
        __syncthreads();
        if (tid < WW) {
            unsigned int run = 0;
            for (int hh = 0; hh < HH; hh++) { run += s[hh * WW + tid]; s[hh * WW + tid] = run; }
        }
        __syncthreads();
        if (tid < HH) {
            unsigned int run = 0;
            for (int w = 0; w < WW; w++) { run += s[tid * WW + w]; s[tid * WW + w] = run; }
        }
        __syncthreads();
        for (int i = tid; i < HH * WW; i += blockDim.x)
            g_cell[(size_t)i * NB + bin] = s[i];
        __syncthreads();
    }

    // ---- grid barrier 2: only block 0 waits; others arrive & exit ----
    __threadfence();
    __syncthreads();
    if (tid == 0) atomicAdd(&g_bar, 1u);
    if (blockIdx.x != 0) return;
    if (tid == 0) { while (atomicAdd(&g_bar, 0u) < 224u) { } }
    __syncthreads();
    __threadfence();

    // ---- phase 3: greedy EKLM loop (block 0, 256 threads) ----
    int xd = 1, ys = g_ys0, yd = g_ys0 + 1;
    float total = g_total_ent;
    float Ts = region_ent(xd, ys, yd, tid) / total;
    bool done = false;
    for (int it = 0; it < 8192; it++) {
        if (!(Ts < T_THRESH && !done)) break;
        float e_cur = region_ent(xd, ys, yd, tid);
        bool c1 = false, c2 = false, c3 = false;
        if (xd + 1 < HH)        c1 = region_ent(xd + 1, ys, yd, tid) > e_cur;
        if (!c1 && ys - 1 >= 0) c2 = region_ent(xd, ys - 1, yd, tid) > e_cur;
        if (!c1 && !c2 && yd + 1 < WW)
            c3 = region_ent(xd, ys, yd + 1, tid) > e_cur;
        if (c1) xd = xd + 1;
        if (c2) ys = ys - 1;
        if (c3) yd = yd + 1;
        done = !(c1 || c2 || c3);
        Ts = region_ent(xd, ys, yd, tid) / total;
    }
    if (tid == 0) {
        g_region[0] = 0; g_region[1] = xd;
        g_region[2] = ys; g_region[3] = yd;
        g_bar = 0u;   // reset barrier for next replay
    }
}

// ------------------------- k4: fused pool + GEMM (block per batch b) ---------
__global__ void __launch_bounds__(256) k_poolgemm(const float* __restrict__ x,
                                                  const float* __restrict__ wfc,
                                                  float* __restrict__ out) {
    __shared__ float sp[CHANNELS];   // 4KB pooled channels for this b
    int b = blockIdx.x;
    int xd = g_region[1], ys = g_region[2], yd = g_region[3];
    int wlen = yd - ys;
    int cnt = xd * wlen;
    float inv = 1.0f / (float)(cnt > 0 ? cnt : 1);

    // pool: thread handles channels c, c+256, c+512, c+768 (independent loads)
    for (int c = threadIdx.x; c < CHANNELS; c += 256) {
        const float* p = x + ((size_t)(b * CHANNELS + c)) * PLANE;
        float s = 0.0f;
        for (int i = 0; i < cnt; i++) {
            int hh = i / wlen;
            int ww = ys + (i - hh * wlen);
            s += p[hh * WW + ww];
        }
        sp[c] = s * inv;
    }
    __syncthreads();

    // gemm: warp per output column n
    int wrp = threadIdx.x >> 5, lane = threadIdx.x & 31;
    for (int n = wrp; n < 30; n += 8) {
        float acc = 0.0f;
        #pragma unroll
        for (int k = 0; k < 32; k++) {
            int c = lane + k * 32;
            acc += sp[c] * wfc[c * 30 + n];
        }
        acc = warpReduceSum(acc);
        if (lane == 0) out[b * 30 + n] = acc;
    }
}

// ------------------------- launch -------------------------------------------
extern "C" void kernel_launch(void* const* d_in, const int* in_sizes, int n_in,
                              void* d_out, int out_size) {
    const float* x   = (const float*)d_in[0];
    const float* wfc = (const float*)d_in[1];
    float* out = (float*)d_out;

    k_hist<<<HIST_BLOCKS, HIST_THREADS>>>((const float4*)x);
    k_decide<<<1, 256>>>();
    k_heavy<<<112, 256>>>(x);      // flag-gated, statistically dead
    k_poolgemm<<<BATCH, 256>>>(x, wfc, out);
}

// round 6
// speedup vs baseline: 1.2147x; 1.2147x over previous
#include <cuda_runtime.h>
#include <math.h>

#define HH 56
#define WW 56
#define NB 256
#define BATCH 8
#define CHANNELS 1024
#define PLANE (HH*WW)           // 3136
#define BC (BATCH*CHANNELS)     // 8192
#define NELEM (BC*PLANE)        // 25,690,112
#define N4 (NELEM/4)            // 6,422,528 float4
#define T_THRESH 0.9f

#define HIST_BLOCKS 592
#define HIST_THREADS 512

// ------------------------- device scratch (no allocations) -------------------
__device__ unsigned int g_total[NB];          // zeroed by k_decide each replay
__device__ unsigned int g_col0[WW*NB];        // zeroed by k_decide each replay
__device__ unsigned int g_cell[HH*WW*NB];     // heavy path scratch (12.8MB)
__device__ unsigned int g_bar;                // heavy path grid barrier
__device__ int   g_region[4];                 // xs, xd, ys, yd
__device__ int   g_flag;                      // 1 => heavy path needed
__device__ float g_total_ent;
__device__ int   g_ys0;
__device__ float g_pooled[BC];

// ------------------------- helpers ------------------------------------------
__device__ __forceinline__ float blockReduceSum(float v) {
    __shared__ float s_red[32];
    unsigned lane = threadIdx.x & 31u;
    unsigned wid  = threadIdx.x >> 5;
    #pragma unroll
    for (int o = 16; o; o >>= 1) v += __shfl_xor_sync(0xffffffffu, v, o);
    if (lane == 0) s_red[wid] = v;
    __syncthreads();
    unsigned nw = (blockDim.x + 31u) >> 5;
    if (wid == 0) {
        float t = (lane < nw) ? s_red[lane] : 0.0f;
        #pragma unroll
        for (int o = 16; o; o >>= 1) t += __shfl_xor_sync(0xffffffffu, t, o);
        if (lane == 0) s_red[0] = t;
    }
    __syncthreads();
    float r = s_red[0];
    __syncthreads();
    return r;
}

__device__ __forceinline__ float warpReduceSum(float v) {
    #pragma unroll
    for (int o = 16; o; o >>= 1) v += __shfl_xor_sync(0xffffffffu, v, o);
    return v;
}

__device__ __forceinline__ int bin_of(float v) {   // caller guarantees v >= 0
    int b = (int)(v * 256.0f);
    return b > 255 ? 255 : b;
}

// ------------------------- k1: fused total + column-0 histograms -------------
__device__ __forceinline__ void hist_one(unsigned int* h, float4 v, int i) {
    int b0 = bin_of(v.x), b1 = bin_of(v.y), b2 = bin_of(v.z), b3 = bin_of(v.w);
    bool v0 = (v.x >= 0.0f && v.x <= 1.0f);
    bool v1 = (v.y >= 0.0f && v.y <= 1.0f);
    bool v2 = (v.z >= 0.0f && v.z <= 1.0f);
    bool v3 = (v.w >= 0.0f && v.w <= 1.0f);
    if (v0) atomicAdd(&h[b0], 1u);
    if (v1) atomicAdd(&h[b1], 1u);
    if (v2) atomicAdd(&h[b2], 1u);
    if (v3) atomicAdd(&h[b3], 1u);
    int m = i % 784;                 // h==0 iff (i % 784) < 14
    if (m < 14) {
        int w = 4 * m;
        if (v0) atomicAdd(&g_col0[(w + 0) * NB + b0], 1u);
        if (v1) atomicAdd(&g_col0[(w + 1) * NB + b1], 1u);
        if (v2) atomicAdd(&g_col0[(w + 2) * NB + b2], 1u);
        if (v3) atomicAdd(&g_col0[(w + 3) * NB + b3], 1u);
    }
}

__global__ void __launch_bounds__(HIST_THREADS) k_hist(const float4* __restrict__ x4) {
    __shared__ unsigned int sh[16 * NB];   // per-warp replicas, 16KB
    for (int i = threadIdx.x; i < 16 * NB; i += blockDim.x) sh[i] = 0u;
    __syncthreads();
    unsigned int* h = sh + (threadIdx.x >> 5) * NB;
    const int stride = HIST_BLOCKS * HIST_THREADS;
    int i = blockIdx.x * HIST_THREADS + threadIdx.x;
    // 2-wide unrolled grid-stride for load MLP
    for (; i + stride < N4; i += 2 * stride) {
        float4 a = x4[i];
        float4 b = x4[i + stride];
        hist_one(h, a, i);
        hist_one(h, b, i + stride);
    }
    if (i < N4) hist_one(h, x4[i], i);
    __syncthreads();
    if (threadIdx.x < NB) {
        unsigned int s = 0;
        #pragma unroll
        for (int r = 0; r < 16; r++) s += sh[r * NB + threadIdx.x];
        atomicAdd(&g_total[threadIdx.x], s);
    }
}

// ------------------------- k2: decide (entropies + argmax + flag) ------------
__global__ void k_decide() {   // 1 block, 256 threads
    int tid = threadIdx.x;
    int lane = tid & 31, wrp = tid >> 5;

    // total entropy (tid == bin)
    float c = (float)g_total[tid];
    float s = blockReduceSum(c);
    float p = c / s;
    float tot = -blockReduceSum(p * log2f(p + 1e-9f));

    // per-column entropies: warp per column
    __shared__ float s_ent[WW];
    for (int w = wrp; w < WW; w += 8) {
        float cs = 0.0f;
        float cc[8];
        #pragma unroll
        for (int k = 0; k < 8; k++) {
            cc[k] = (float)g_col0[w * NB + lane + k * 32];
            cs += cc[k];
        }
        cs = warpReduceSum(cs);
        float e = 0.0f;
        #pragma unroll
        for (int k = 0; k < 8; k++) {
            float pp = cc[k] / cs;
            e += pp * log2f(pp + 1e-9f);
        }
        e = -warpReduceSum(e);
        if (lane == 0) s_ent[w] = e;
    }
    __syncthreads();
    if (tid == 0) {
        float bestEnt = -1e30f; int bestw = 0;
        for (int w = 0; w < WW; w++)
            if (s_ent[w] > bestEnt) { bestEnt = s_ent[w]; bestw = w; }
        float Ts0 = bestEnt / tot;
        if (Ts0 < T_THRESH) {
            g_flag = 1;
            g_ys0 = bestw;
            g_total_ent = tot;
        } else {
            g_flag = 0;
            g_region[0] = 0; g_region[1] = 1;
            g_region[2] = bestw; g_region[3] = bestw + 1;
        }
    }
    __syncthreads();
    // re-zero accumulators for the next graph replay
    g_total[tid] = 0u;
    for (int j = tid; j < WW * NB; j += 256) g_col0[j] = 0u;
}

// ------------------------- k3: heavy path, ONE kernel (flag-gated) -----------
__device__ __forceinline__ float integA(int i, int j, int tid) {
    if (i <= 0 || j <= 0) return 0.0f;
    return (float)g_cell[((size_t)((i - 1) * WW + (j - 1))) * NB + tid];
}

__device__ float region_ent(int xd, int ys, int yd, int tid) {
    float a = integA(xd, yd, tid) - integA(xd, ys, tid);
    float s = blockReduceSum(a);
    float p = a / s;
    return -blockReduceSum(p * log2f(p + 1e-9f));
}

// 112 blocks (single wave, all resident), 256 threads, 28KB smem
__global__ void __launch_bounds__(256) k_heavy(const float* __restrict__ x) {
    if (!g_flag) return;
    __shared__ unsigned int sh[28 * NB];   // 28KB; phase2 reuses first 12.5KB
    int tid = threadIdx.x;

    // ---- phase 1: per-(h,w)-cell histograms (block owns 28 cells) ----
    for (int i = tid; i < 28 * NB; i += blockDim.x) sh[i] = 0u;
    __syncthreads();
    int h     = blockIdx.x >> 1;
    int whalf = blockIdx.x & 1;
    const int TOT = BC * 28;
    for (int i = tid; i < TOT; i += blockDim.x) {
        int bc   = i / 28;
        int wloc = i % 28;
        float v = x[(size_t)bc * PLANE + h * WW + whalf * 28 + wloc];
        if (v >= 0.0f && v <= 1.0f)
            atomicAdd(&sh[wloc * NB + bin_of(v)], 1u);
    }
    __syncthreads();
    for (int i = tid; i < 28 * NB; i += blockDim.x)
        g_cell[((size_t)(h * WW + whalf * 28 + (i >> 8))) * NB + (i & 255)] = sh[i];

    // ---- grid barrier 1 (all 112 blocks resident: single wave) ----
    __threadfence();
    __syncthreads();
    if (tid == 0) atomicAdd(&g_bar, 1u);
    if (tid == 0) { while (atomicAdd(&g_bar, 0u) < 112u) { } }
    __syncthreads();
    __threadfence();

    // ---- phase 2: 2D integral per bin ----
    unsigned int* s = sh;   // reuse: HH*WW = 3136 words
    for (int bin = blockIdx.x; bin < NB; bin += gridDim.x) {
        for (int i = tid; i < HH * WW; i += blockDim.x)
            s[i] = g_cell[(size_t)i * NB + bin];
        __syncthreads();
        if (tid < WW) {
            unsigned int run = 0;
            for (int hh = 0; hh < HH; hh++) { run += s[hh * WW + tid]; s[hh * WW + tid] = run; }
        }
        __syncthreads();
        if (tid < HH) {
            unsigned int run = 0;
            for (int w = 0; w < WW; w++) { run += s[tid * WW + w]; s[tid * WW + w] = run; }
        }
        __syncthreads();
        for (int i = tid; i < HH * WW; i += blockDim.x)
            g_cell[(size_t)i * NB + bin] = s[i];
        __syncthreads();
    }

    // ---- grid barrier 2: only block 0 waits; others arrive & exit ----
    __threadfence();
    __syncthreads();
    if (tid == 0) atomicAdd(&g_bar, 1u);
    if (blockIdx.x != 0) return;
    if (tid == 0) { while (atomicAdd(&g_bar, 0u) < 224u) { } }
    __syncthreads();
    __threadfence();

    // ---- phase 3: greedy EKLM loop (block 0, 256 threads) ----
    int xd = 1, ys = g_ys0, yd = g_ys0 + 1;
    float total = g_total_ent;
    float Ts = region_ent(xd, ys, yd, tid) / total;
    bool done = false;
    for (int it = 0; it < 8192; it++) {
        if (!(Ts < T_THRESH && !done)) break;
        float e_cur = region_ent(xd, ys, yd, tid);
        bool c1 = false, c2 = false, c3 = false;
        if (xd + 1 < HH)        c1 = region_ent(xd + 1, ys, yd, tid) > e_cur;
        if (!c1 && ys - 1 >= 0) c2 = region_ent(xd, ys - 1, yd, tid) > e_cur;
        if (!c1 && !c2 && yd + 1 < WW)
            c3 = region_ent(xd, ys, yd + 1, tid) > e_cur;
        if (c1) xd = xd + 1;
        if (c2) ys = ys - 1;
        if (c3) yd = yd + 1;
        done = !(c1 || c2 || c3);
        Ts = region_ent(xd, ys, yd, tid) / total;
    }
    if (tid == 0) {
        g_region[0] = 0; g_region[1] = xd;
        g_region[2] = ys; g_region[3] = yd;
        g_bar = 0u;   // reset barrier for next replay
    }
}

// ------------------------- k4: region mean-pool, THREAD per (b,c) ------------
// 64 blocks x 128 threads = 8192 threads, one per (b,c)
__global__ void __launch_bounds__(128) k_pool(const float* __restrict__ x) {
    int bc = blockIdx.x * 128 + threadIdx.x;
    int xd = g_region[1], ys = g_region[2], yd = g_region[3];
    int wlen = yd - ys;
    int cnt = xd * wlen;
    const float* p = x + (size_t)bc * PLANE;
    float s0 = 0.f, s1 = 0.f, s2 = 0.f, s3 = 0.f;
    int i = 0;
    for (; i + 4 <= cnt; i += 4) {      // 4-wide for MLP
        int h0 = (i + 0) / wlen, w0 = ys + (i + 0) - h0 * wlen;
        int h1 = (i + 1) / wlen, w1 = ys + (i + 1) - h1 * wlen;
        int h2 = (i + 2) / wlen, w2 = ys + (i + 2) - h2 * wlen;
        int h3 = (i + 3) / wlen, w3 = ys + (i + 3) - h3 * wlen;
        s0 += p[h0 * WW + w0];
        s1 += p[h1 * WW + w1];
        s2 += p[h2 * WW + w2];
        s3 += p[h3 * WW + w3];
    }
    for (; i < cnt; i++) {
        int hh = i / wlen;
        int ww = ys + (i - hh * wlen);
        s0 += p[hh * WW + ww];
    }
    float s = (s0 + s1) + (s2 + s3);
    g_pooled[bc] = s / (float)(cnt > 0 ? cnt : 1);
}

// ------------------------- k5: tiny GEMM, block per output element -----------
__global__ void k_gemm(const float* __restrict__ wfc, float* __restrict__ out) {
    int b = blockIdx.x / 30;
    int n = blockIdx.x % 30;
    int tid = threadIdx.x;
    const float* pb = g_pooled + b * CHANNELS;
    float acc = 0.0f;
    #pragma unroll
    for (int k = 0; k < 4; k++) {
        int c = tid + k * 256;
        acc += pb[c] * wfc[c * 30 + n];
    }
    acc = blockReduceSum(acc);
    if (tid == 0) out[b * 30 + n] = acc;
}

// ------------------------- launch -------------------------------------------
extern "C" void kernel_launch(void* const* d_in, const int* in_sizes, int n_in,
                              void* d_out, int out_size) {
    const float* x   = (const float*)d_in[0];
    const float* wfc = (const float*)d_in[1];
    float* out = (float*)d_out;

    k_hist<<<HIST_BLOCKS, HIST_THREADS>>>((const float4*)x);
    k_decide<<<1, 256>>>();
    k_heavy<<<112, 256>>>(x);      // flag-gated, statistically dead
    k_pool<<<BC / 128, 128>>>(x);
    k_gemm<<<240, 256>>>(wfc, out);
}

// round 7
// speedup vs baseline: 2.1047x; 1.7327x over previous
#include <cuda_runtime.h>
#include <math.h>

#define HH 56
#define WW 56
#define NB 256
#define BATCH 8
#define CHANNELS 1024
#define PLANE (HH*WW)           // 3136
#define BC (BATCH*CHANNELS)     // 8192
#define NELEM (BC*PLANE)        // 25,690,112
#define N4 (NELEM/4)            // 6,422,528 float4
#define T_THRESH 0.9f

#define HIST_BLOCKS 592
#define HIST_THREADS 512

// ------------------------- device scratch (no allocations) -------------------
__device__ unsigned int g_total[NB];          // zero-init; re-zeroed if used
__device__ float g_ent_y[WW];
__device__ unsigned int g_cell[HH*WW*NB];     // heavy path scratch (12.8MB)
__device__ unsigned int g_bar;                // heavy path grid barrier
__device__ unsigned int g_bar2;               // colent grid barrier
__device__ int   g_region[4];                 // xs, xd, ys, yd
__device__ int   g_flag;                      // 1 => heavy greedy loop needed
__device__ int   g_need_full;                 // 1 => full hist + ratio test needed
__device__ float g_best_ent;
__device__ float g_total_ent;
__device__ int   g_ys0;

// ------------------------- helpers ------------------------------------------
__device__ __forceinline__ float blockReduceSum(float v) {
    __shared__ float s_red[32];
    unsigned lane = threadIdx.x & 31u;
    unsigned wid  = threadIdx.x >> 5;
    #pragma unroll
    for (int o = 16; o; o >>= 1) v += __shfl_xor_sync(0xffffffffu, v, o);
    if (lane == 0) s_red[wid] = v;
    __syncthreads();
    unsigned nw = (blockDim.x + 31u) >> 5;
    if (wid == 0) {
        float t = (lane < nw) ? s_red[lane] : 0.0f;
        #pragma unroll
        for (int o = 16; o; o >>= 1) t += __shfl_xor_sync(0xffffffffu, t, o);
        if (lane == 0) s_red[0] = t;
    }
    __syncthreads();
    float r = s_red[0];
    __syncthreads();
    return r;
}

__device__ __forceinline__ int bin_of(float v) {   // caller guarantees v >= 0
    int b = (int)(v * 256.0f);
    return b > 255 ? 255 : b;
}

// ---------- k1: per-column entropies + decide (56 blocks, 256 thr) -----------
// Bound argument: total_ent = -sum p*log2(p+1e-9) <= -sum p*log2(p) <= log2(256) = 8.
// So bestEnt >= 7.2  =>  Ts0 = bestEnt/total_ent >= bestEnt/8 >= 0.9  => loop dead,
// region = (0,1,ys0,ys0+1) EXACTLY as the reference computes. Otherwise fall back
// to the gated full-histogram path below (bit-identical to prior rounds).
__global__ void __launch_bounds__(256) k_colent_decide(const float* __restrict__ x) {
    __shared__ unsigned int sh[8 * NB];   // per-warp replicas, 8KB
    int tid = threadIdx.x;
    int w = blockIdx.x;
    for (int i = tid; i < 8 * NB; i += 256) sh[i] = 0u;
    __syncthreads();
    unsigned int* h = sh + (tid >> 5) * NB;
    // column w of row 0 across all (b,c) planes
    for (int bc = tid; bc < BC; bc += 256) {
        float v = x[(size_t)bc * PLANE + w];
        if (v >= 0.0f && v <= 1.0f) atomicAdd(&h[bin_of(v)], 1u);
    }
    __syncthreads();
    unsigned int cu = 0;
    #pragma unroll
    for (int r = 0; r < 8; r++) cu += sh[r * NB + tid];
    float c = (float)cu;
    float s = blockReduceSum(c);
    float p = c / s;
    float ent = -blockReduceSum(p * log2f(p + 1e-9f));
    if (tid == 0) g_ent_y[w] = ent;

    // ---- grid barrier: 56 blocks, single wave ----
    __threadfence();
    __syncthreads();
    if (tid == 0) atomicAdd(&g_bar2, 1u);
    if (blockIdx.x != 0) return;
    if (tid == 0) { while (atomicAdd(&g_bar2, 0u) < (unsigned)WW) { } }
    __syncthreads();
    __threadfence();

    // ---- block 0: argmax + bound test ----
    if (tid == 0) {
        float bestEnt = -1e30f; int bestw = 0;
        for (int ww2 = 0; ww2 < WW; ww2++) {
            float e = g_ent_y[ww2];
            if (e > bestEnt) { bestEnt = e; bestw = ww2; }
        }
        g_ys0 = bestw;
        g_best_ent = bestEnt;
        if (bestEnt >= T_THRESH * 8.0f) {
            // provably Ts0 >= 0.9: loop never runs
            g_need_full = 0;
            g_flag = 0;
            g_region[0] = 0; g_region[1] = 1;
            g_region[2] = bestw; g_region[3] = bestw + 1;
        } else {
            g_need_full = 1;
        }
        g_bar2 = 0u;   // reset for next replay
    }
}

// ------------------------- k2: full histogram (gated) ------------------------
__device__ __forceinline__ void hist_one(unsigned int* h, float4 v) {
    if (v.x >= 0.0f && v.x <= 1.0f) atomicAdd(&h[bin_of(v.x)], 1u);
    if (v.y >= 0.0f && v.y <= 1.0f) atomicAdd(&h[bin_of(v.y)], 1u);
    if (v.z >= 0.0f && v.z <= 1.0f) atomicAdd(&h[bin_of(v.z)], 1u);
    if (v.w >= 0.0f && v.w <= 1.0f) atomicAdd(&h[bin_of(v.w)], 1u);
}

__global__ void __launch_bounds__(HIST_THREADS) k_hist(const float4* __restrict__ x4) {
    if (!g_need_full) return;
    __shared__ unsigned int sh[16 * NB];   // per-warp replicas, 16KB
    for (int i = threadIdx.x; i < 16 * NB; i += blockDim.x) sh[i] = 0u;
    __syncthreads();
    unsigned int* h = sh + (threadIdx.x >> 5) * NB;
    const int stride = HIST_BLOCKS * HIST_THREADS;
    int i = blockIdx.x * HIST_THREADS + threadIdx.x;
    for (; i + stride < N4; i += 2 * stride) {
        float4 a = x4[i];
        float4 b = x4[i + stride];
        hist_one(h, a);
        hist_one(h, b);
    }
    if (i < N4) hist_one(h, x4[i]);
    __syncthreads();
    if (threadIdx.x < NB) {
        unsigned int s = 0;
        #pragma unroll
        for (int r = 0; r < 16; r++) s += sh[r * NB + threadIdx.x];
        atomicAdd(&g_total[threadIdx.x], s);
    }
}

// ------------------------- k3: full decide (gated) ---------------------------
__global__ void k_decide_full() {   // 1 block, 256 threads (tid == bin)
    if (!g_need_full) return;
    int tid = threadIdx.x;
    float c = (float)g_total[tid];
    float s = blockReduceSum(c);
    float p = c / s;
    float tot = -blockReduceSum(p * log2f(p + 1e-9f));
    if (tid == 0) {
        float Ts0 = g_best_ent / tot;
        if (Ts0 < T_THRESH) {
            g_flag = 1;
            g_total_ent = tot;
        } else {
            g_flag = 0;
            int bestw = g_ys0;
            g_region[0] = 0; g_region[1] = 1;
            g_region[2] = bestw; g_region[3] = bestw + 1;
        }
    }
    __syncthreads();
    g_total[tid] = 0u;     // re-zero for next use
    if (tid == 0) g_need_full = 0;   // consumed
}

// ------------------------- k4: heavy path, ONE kernel (flag-gated) -----------
__device__ __forceinline__ float integA(int i, int j, int tid) {
    if (i <= 0 || j <= 0) return 0.0f;
    return (float)g_cell[((size_t)((i - 1) * WW + (j - 1))) * NB + tid];
}

__device__ float region_ent(int xd, int ys, int yd, int tid) {
    float a = integA(xd, yd, tid) - integA(xd, ys, tid);
    float s = blockReduceSum(a);
    float p = a / s;
    return -blockReduceSum(p * log2f(p + 1e-9f));
}

// 112 blocks (single wave), 256 threads, 28KB smem
__global__ void __launch_bounds__(256) k_heavy(const float* __restrict__ x) {
    if (!g_flag) return;
    __shared__ unsigned int sh[28 * NB];   // 28KB
    int tid = threadIdx.x;

    // ---- phase 1: per-(h,w)-cell histograms (block owns 28 cells) ----
    for (int i = tid; i < 28 * NB; i += blockDim.x) sh[i] = 0u;
    __syncthreads();
    int h     = blockIdx.x >> 1;
    int whalf = blockIdx.x & 1;
    const int TOT = BC * 28;
    for (int i = tid; i < TOT; i += blockDim.x) {
        int bc   = i / 28;
        int wloc = i % 28;
        float v = x[(size_t)bc * PLANE + h * WW + whalf * 28 + wloc];
        if (v >= 0.0f && v <= 1.0f)
            atomicAdd(&sh[wloc * NB + bin_of(v)], 1u);
    }
    __syncthreads();
    for (int i = tid; i < 28 * NB; i += blockDim.x)
        g_cell[((size_t)(h * WW + whalf * 28 + (i >> 8))) * NB + (i & 255)] = sh[i];

    // ---- grid barrier 1 ----
    __threadfence();
    __syncthreads();
    if (tid == 0) atomicAdd(&g_bar, 1u);
    if (tid == 0) { while (atomicAdd(&g_bar, 0u) < 112u) { } }
    __syncthreads();
    __threadfence();

    // ---- phase 2: 2D integral per bin ----
    unsigned int* s = sh;
    for (int bin = blockIdx.x; bin < NB; bin += gridDim.x) {
        for (int i = tid; i < HH * WW; i += blockDim.x)
            s[i] = g_cell[(size_t)i * NB + bin];
        __syncthreads();
        if (tid < WW) {
            unsigned int run = 0;
            for (int hh = 0; hh < HH; hh++) { run += s[hh * WW + tid]; s[hh * WW + tid] = run; }
        }
        __syncthreads();
        if (tid < HH) {
            unsigned int run = 0;
            for (int w = 0; w < WW; w++) { run += s[tid * WW + w]; s[tid * WW + w] = run; }
        }
        __syncthreads();
        for (int i = tid; i < HH * WW; i += blockDim.x)
            g_cell[(size_t)i * NB + bin] = s[i];
        __syncthreads();
    }

    // ---- grid barrier 2: block 0 waits; others exit ----
    __threadfence();
    __syncthreads();
    if (tid == 0) atomicAdd(&g_bar, 1u);
    if (blockIdx.x != 0) return;
    if (tid == 0) { while (atomicAdd(&g_bar, 0u) < 224u) { } }
    __syncthreads();
    __threadfence();

    // ---- phase 3: greedy EKLM loop (block 0) ----
    int xd = 1, ys = g_ys0, yd = g_ys0 + 1;
    float total = g_total_ent;
    float Ts = region_ent(xd, ys, yd, tid) / total;
    bool done = false;
    for (int it = 0; it < 8192; it++) {
        if (!(Ts < T_THRESH && !done)) break;
        float e_cur = region_ent(xd, ys, yd, tid);
        bool c1 = false, c2 = false, c3 = false;
        if (xd + 1 < HH)        c1 = region_ent(xd + 1, ys, yd, tid) > e_cur;
        if (!c1 && ys - 1 >= 0) c2 = region_ent(xd, ys - 1, yd, tid) > e_cur;
        if (!c1 && !c2 && yd + 1 < WW)
            c3 = region_ent(xd, ys, yd + 1, tid) > e_cur;
        if (c1) xd = xd + 1;
        if (c2) ys = ys - 1;
        if (c3) yd = yd + 1;
        done = !(c1 || c2 || c3);
        Ts = region_ent(xd, ys, yd, tid) / total;
    }
    if (tid == 0) {
        g_region[0] = 0; g_region[1] = xd;
        g_region[2] = ys; g_region[3] = yd;
        g_bar = 0u;
    }
}

// ------------------------- k5: fused pool+GEMM, block per (b,n) --------------
__global__ void __launch_bounds__(256) k_poolgemm(const float* __restrict__ x,
                                                  const float* __restrict__ wfc,
                                                  float* __restrict__ out) {
    int b = blockIdx.x / 30;
    int n = blockIdx.x % 30;
    int tid = threadIdx.x;
    int xd = g_region[1], ys = g_region[2], yd = g_region[3];
    int wlen = yd - ys;
    int cnt = xd * wlen;
    float inv = 1.0f / (float)(cnt > 0 ? cnt : 1);

    float acc = 0.0f;
    #pragma unroll
    for (int k = 0; k < 4; k++) {
        int c = tid + k * 256;
        const float* p = x + ((size_t)(b * CHANNELS + c)) * PLANE;
        float s = 0.0f;
        for (int i = 0; i < cnt; i++) {
            int hh = i / wlen;
            int ww = ys + (i - hh * wlen);
            s += p[hh * WW + ww];
        }
        acc += s * wfc[c * 30 + n];
    }
    acc = blockReduceSum(acc);
    if (tid == 0) out[b * 30 + n] = acc * inv;
}

// ------------------------- launch -------------------------------------------
extern "C" void kernel_launch(void* const* d_in, const int* in_sizes, int n_in,
                              void* d_out, int out_size) {
    const float* x   = (const float*)d_in[0];
    const float* wfc = (const float*)d_in[1];
    float* out = (float*)d_out;

    k_colent_decide<<<WW, 256>>>(x);
    k_hist<<<HIST_BLOCKS, HIST_THREADS>>>((const float4*)x);   // gated
    k_decide_full<<<1, 256>>>();                               // gated
    k_heavy<<<112, 256>>>(x);                                  // gated
    k_poolgemm<<<240, 256>>>(x, wfc, out);
}

// round 8
// speedup vs baseline: 2.2683x; 1.0777x over previous
#include <cuda_runtime.h>
#include <math.h>

#define HH 56
#define WW 56
#define NB 256
#define BATCH 8
#define CHANNELS 1024
#define PLANE (HH*WW)           // 3136
#define BC (BATCH*CHANNELS)     // 8192
#define NELEM (BC*PLANE)        // 25,690,112
#define N4 (NELEM/4)            // 6,422,528 float4
#define T_THRESH 0.9f

#define NBLK 240
#define NTHR 256

// ------------------------- device scratch (no allocations) -------------------
__device__ unsigned int g_cnt[8];             // barrier arrive counters (self-reset)
__device__ unsigned int g_gen[8];             // barrier generations (monotonic)
__device__ unsigned int g_col0[WW*NB];        // zero-init; re-zeroed each replay
__device__ unsigned int g_total[NB];          // zero-init; re-zeroed when used
__device__ float g_ent_y[WW];
__device__ unsigned int g_cell[HH*WW*NB];     // fallback integral-hist (12.8MB)
__device__ int   g_region[4];
__device__ int   g_flag;
__device__ int   g_need_full;
__device__ float g_best_ent;
__device__ float g_total_ent;
__device__ int   g_ys0;

// ------------------------- helpers ------------------------------------------
__device__ __forceinline__ float blockReduceSum(float v) {
    __shared__ float s_red[32];
    unsigned lane = threadIdx.x & 31u;
    unsigned wid  = threadIdx.x >> 5;
    #pragma unroll
    for (int o = 16; o; o >>= 1) v += __shfl_xor_sync(0xffffffffu, v, o);
    if (lane == 0) s_red[wid] = v;
    __syncthreads();
    unsigned nw = (blockDim.x + 31u) >> 5;
    if (wid == 0) {
        float t = (lane < nw) ? s_red[lane] : 0.0f;
        #pragma unroll
        for (int o = 16; o; o >>= 1) t += __shfl_xor_sync(0xffffffffu, t, o);
        if (lane == 0) s_red[0] = t;
    }
    __syncthreads();
    float r = s_red[0];
    __syncthreads();
    return r;
}

__device__ __forceinline__ int bin_of(float v) {   // caller guarantees v >= 0
    int b = (int)(v * 256.0f);
    return b > 255 ? 255 : b;
}

// Grid barrier: generation-monotonic (replay-safe), arrive-counter self-resets.
// Requires all NBLK blocks resident (single wave) and uniform participation.
__device__ __forceinline__ void gridbar(int i) {
    __syncthreads();
    if (threadIdx.x == 0) {
        __threadfence();
        unsigned gen = atomicAdd(&g_gen[i], 0u);          // read BEFORE arriving
        unsigned arrived = atomicAdd(&g_cnt[i], 1u) + 1u;
        if (arrived == (unsigned)NBLK) {
            g_cnt[i] = 0u;
            __threadfence();
            atomicAdd(&g_gen[i], 1u);                     // release
        } else {
            while (atomicAdd(&g_gen[i], 0u) == gen) { }
        }
        __threadfence();
    }
    __syncthreads();
}

__device__ __forceinline__ void hist_one(unsigned int* h, float4 v) {
    if (v.x >= 0.0f && v.x <= 1.0f) atomicAdd(&h[bin_of(v.x)], 1u);
    if (v.y >= 0.0f && v.y <= 1.0f) atomicAdd(&h[bin_of(v.y)], 1u);
    if (v.z >= 0.0f && v.z <= 1.0f) atomicAdd(&h[bin_of(v.z)], 1u);
    if (v.w >= 0.0f && v.w <= 1.0f) atomicAdd(&h[bin_of(v.w)], 1u);
}

__device__ __forceinline__ float integA(int i, int j, int tid) {
    if (i <= 0 || j <= 0) return 0.0f;
    return (float)g_cell[((size_t)((i - 1) * WW + (j - 1))) * NB + tid];
}

__device__ float region_ent(int xd, int ys, int yd, int tid) {
    float a = integA(xd, yd, tid) - integA(xd, ys, tid);
    float s = blockReduceSum(a);
    float p = a / s;
    return -blockReduceSum(p * log2f(p + 1e-9f));
}

// ------------------------- THE kernel ----------------------------------------
__global__ void __launch_bounds__(NTHR) k_mega(const float* __restrict__ x,
                                               const float* __restrict__ wfc,
                                               float* __restrict__ out) {
    __shared__ unsigned int sh[4096];   // 16KB scratch, reused across phases
    const int tid = threadIdx.x;
    const int bb  = blockIdx.x;

    // ===== Phase A: column-0 histograms, 4 blocks per column (blocks 0..223) ==
    if (bb < 224) {
        for (int i = tid; i < 8 * NB; i += NTHR) sh[i] = 0u;
        __syncthreads();
        int w    = bb >> 2;
        int part = bb & 3;
        unsigned int* h = sh + (tid >> 5) * NB;
        int bc0 = part * (BC / 4);
        for (int bc = bc0 + tid; bc < bc0 + BC / 4; bc += NTHR) {
            float v = x[(size_t)bc * PLANE + w];   // h == 0
            if (v >= 0.0f && v <= 1.0f) atomicAdd(&h[bin_of(v)], 1u);
        }
        __syncthreads();
        unsigned int s = 0;
        #pragma unroll
        for (int r = 0; r < 8; r++) s += sh[r * NB + tid];
        if (s) atomicAdd(&g_col0[w * NB + tid], s);
    }
    gridbar(0);

    // ===== Phase B: per-column entropy (blocks 0..55), then re-zero g_col0 ====
    if (bb < WW) {
        unsigned int cu = g_col0[bb * NB + tid];
        g_col0[bb * NB + tid] = 0u;                 // ready for next replay
        float c = (float)cu;
        float s = blockReduceSum(c);
        float p = c / s;
        float ent = -blockReduceSum(p * log2f(p + 1e-9f));
        if (tid == 0) g_ent_y[bb] = ent;
    }
    gridbar(1);

    // ===== Decide (block 0): argmax + entropy bound test ======================
    // total_ent = -sum p*log2(p+1e-9) <= log2(256) = 8, so
    // bestEnt >= 0.9*8  =>  Ts0 >= 0.9  =>  reference loop provably never runs.
    if (bb == 0 && tid == 0) {
        float bestEnt = -1e30f; int bestw = 0;
        for (int w = 0; w < WW; w++) {
            float e = g_ent_y[w];
            if (e > bestEnt) { bestEnt = e; bestw = w; }
        }
        g_ys0 = bestw;
        g_best_ent = bestEnt;
        if (bestEnt >= T_THRESH * 8.0f) {
            g_need_full = 0;
            g_flag = 0;
            g_region[0] = 0; g_region[1] = 1;
            g_region[2] = bestw; g_region[3] = bestw + 1;
        } else {
            g_need_full = 1;
        }
    }
    gridbar(2);

    // ===== Fallback (uniform branch; statistically dead on this input) ========
    if (g_need_full) {
        // ---- full-image histogram ----
        for (int i = tid; i < 8 * NB; i += NTHR) sh[i] = 0u;
        __syncthreads();
        {
            const float4* x4 = (const float4*)x;
            unsigned int* h = sh + (tid >> 5) * NB;
            const int stride = NBLK * NTHR;
            for (int i = bb * NTHR + tid; i < N4; i += stride)
                hist_one(h, x4[i]);
            __syncthreads();
            unsigned int s = 0;
            #pragma unroll
            for (int r = 0; r < 8; r++) s += sh[r * NB + tid];
            if (s) atomicAdd(&g_total[tid], s);
        }
        gridbar(3);
        // ---- ratio test on block 0 ----
        if (bb == 0) {
            float c = (float)g_total[tid];
            g_total[tid] = 0u;
            float s = blockReduceSum(c);
            float p = c / s;
            float tot = -blockReduceSum(p * log2f(p + 1e-9f));
            if (tid == 0) {
                float Ts0 = g_best_ent / tot;
                if (Ts0 < T_THRESH) {
                    g_flag = 1;
                    g_total_ent = tot;
                } else {
                    g_flag = 0;
                    g_region[0] = 0; g_region[1] = 1;
                    g_region[2] = g_ys0; g_region[3] = g_ys0 + 1;
                }
            }
        }
        gridbar(4);

        if (g_flag) {
            // ---- cell histograms: blocks 0..223 own (h, 14 w's) ----
            if (bb < 224) {
                for (int i = tid; i < 14 * NB; i += NTHR) sh[i] = 0u;
                __syncthreads();
                int h  = bb >> 2;
                int wq = bb & 3;
                const int TOT = BC * 14;
                for (int i = tid; i < TOT; i += NTHR) {
                    int bc   = i / 14;
                    int wloc = i % 14;
                    float v = x[(size_t)bc * PLANE + h * WW + wq * 14 + wloc];
                    if (v >= 0.0f && v <= 1.0f)
                        atomicAdd(&sh[wloc * NB + bin_of(v)], 1u);
                }
                __syncthreads();
                for (int i = tid; i < 14 * NB; i += NTHR)
                    g_cell[((size_t)(h * WW + wq * 14 + (i >> 8))) * NB + (i & 255)] = sh[i];
            }
            gridbar(5);
            // ---- 2D integral per bin (grid-stride) ----
            for (int bin = bb; bin < NB; bin += NBLK) {
                for (int i = tid; i < HH * WW; i += NTHR)
                    sh[i] = g_cell[(size_t)i * NB + bin];
                __syncthreads();
                if (tid < WW) {
                    unsigned int run = 0;
                    for (int hh = 0; hh < HH; hh++) { run += sh[hh * WW + tid]; sh[hh * WW + tid] = run; }
                }
                __syncthreads();
                if (tid < HH) {
                    unsigned int run = 0;
                    for (int w = 0; w < WW; w++) { run += sh[tid * WW + w]; sh[tid * WW + w] = run; }
                }
                __syncthreads();
                for (int i = tid; i < HH * WW; i += NTHR)
                    g_cell[(size_t)i * NB + bin] = sh[i];
                __syncthreads();
            }
            gridbar(6);
            // ---- greedy EKLM loop on block 0 ----
            if (bb == 0) {
                int xd = 1, ys = g_ys0, yd = g_ys0 + 1;
                float total = g_total_ent;
                float Ts = region_ent(xd, ys, yd, tid) / total;
                bool done = false;
                for (int it = 0; it < 8192; it++) {
                    if (!(Ts < T_THRESH && !done)) break;
                    float e_cur = region_ent(xd, ys, yd, tid);
                    bool c1 = false, c2 = false, c3 = false;
                    if (xd + 1 < HH)        c1 = region_ent(xd + 1, ys, yd, tid) > e_cur;
                    if (!c1 && ys - 1 >= 0) c2 = region_ent(xd, ys - 1, yd, tid) > e_cur;
                    if (!c1 && !c2 && yd + 1 < WW)
                        c3 = region_ent(xd, ys, yd + 1, tid) > e_cur;
                    if (c1) xd = xd + 1;
                    if (c2) ys = ys - 1;
                    if (c3) yd = yd + 1;
                    done = !(c1 || c2 || c3);
                    Ts = region_ent(xd, ys, yd, tid) / total;
                }
                if (tid == 0) {
                    g_region[0] = 0; g_region[1] = xd;
                    g_region[2] = ys; g_region[3] = yd;
                }
            }
            gridbar(7);
        }
    }

    // ===== Final: fused pool + GEMM, block per (b, n) =========================
    {
        int b = bb / 30;
        int n = bb % 30;
        int xd = g_region[1], ys = g_region[2], yd = g_region[3];
        int wlen = yd - ys;
        int cnt = xd * wlen;
        float inv = 1.0f / (float)(cnt > 0 ? cnt : 1);

        float acc = 0.0f;
        #pragma unroll
        for (int k = 0; k < 4; k++) {
            int c = tid + k * NTHR;
            const float* p = x + ((size_t)(b * CHANNELS + c)) * PLANE;
            float s = 0.0f;
            for (int i = 0; i < cnt; i++) {
                int hh = i / wlen;
                int ww2 = ys + (i - hh * wlen);
                s += p[hh * WW + ww2];
            }
            acc += s * wfc[c * 30 + n];
        }
        acc = blockReduceSum(acc);
        if (tid == 0) out[b * 30 + n] = acc * inv;
    }
}

// ------------------------- launch -------------------------------------------
extern "C" void kernel_launch(void* const* d_in, const int* in_sizes, int n_in,
                              void* d_out, int out_size) {
    const float* x   = (const float*)d_in[0];
    const float* wfc = (const float*)d_in[1];
    float* out = (float*)d_out;

    k_mega<<<NBLK, NTHR>>>(x, wfc, out);
}

// round 9
// speedup vs baseline: 2.7813x; 1.2262x over previous
#include <cuda_runtime.h>
#include <math.h>

#define HH 56
#define WW 56
#define NB 256
#define BATCH 8
#define CHANNELS 1024
#define PLANE (HH*WW)           // 3136 floats
#define PLANE4 (PLANE/4)        // 784 float4
#define BC (BATCH*CHANNELS)     // 8192
#define NELEM (BC*PLANE)        // 25,690,112
#define N4 (NELEM/4)            // 6,422,528 float4
#define T_THRESH 0.9f

#define NBLK 240
#define NTHR 256

// ------------------------- device scratch (no allocations) -------------------
__device__ unsigned int g_cnt[8];             // barrier arrive counters (self-reset)
__device__ unsigned int g_gen[8];             // barrier generations (monotonic)
__device__ unsigned long long g_best;         // packed (ent_bits<<8)|(255-w), reset at start
__device__ unsigned int g_col0[WW*NB];        // zero-init; re-zeroed each replay
__device__ unsigned int g_total[NB];          // fallback scratch
__device__ unsigned int g_cell[HH*WW*NB];     // fallback integral-hist (12.8MB)
__device__ int   g_region[4];
__device__ int   g_flag;
__device__ float g_total_ent;

// ------------------------- helpers ------------------------------------------
__device__ __forceinline__ float blockReduceSum(float v) {
    __shared__ float s_red[32];
    unsigned lane = threadIdx.x & 31u;
    unsigned wid  = threadIdx.x >> 5;
    #pragma unroll
    for (int o = 16; o; o >>= 1) v += __shfl_xor_sync(0xffffffffu, v, o);
    if (lane == 0) s_red[wid] = v;
    __syncthreads();
    unsigned nw = (blockDim.x + 31u) >> 5;
    if (wid == 0) {
        float t = (lane < nw) ? s_red[lane] : 0.0f;
        #pragma unroll
        for (int o = 16; o; o >>= 1) t += __shfl_xor_sync(0xffffffffu, t, o);
        if (lane == 0) s_red[0] = t;
    }
    __syncthreads();
    float r = s_red[0];
    __syncthreads();
    return r;
}

__device__ __forceinline__ int bin_of(float v) {   // caller guarantees v >= 0
    int b = (int)(v * 256.0f);
    return b > 255 ? 255 : b;
}

// Grid barrier: atomic arrival, VOLATILE-load polling (no RMW spin).
// Generation counter is monotonic => replay-safe. Requires single wave.
__device__ __forceinline__ void gridbar(int i) {
    __syncthreads();
    if (threadIdx.x == 0) {
        __threadfence();
        volatile unsigned* genp = (volatile unsigned*)&g_gen[i];
        unsigned gen = *genp;                              // read BEFORE arriving
        unsigned arrived = atomicAdd(&g_cnt[i], 1u) + 1u;
        if (arrived == (unsigned)NBLK) {
            g_cnt[i] = 0u;
            __threadfence();
            atomicAdd(&g_gen[i], 1u);                      // release
        } else {
            while (*genp == gen) { }
        }
        __threadfence();
    }
    __syncthreads();
}

__device__ __forceinline__ void hist_one(unsigned int* h, float4 v) {
    if (v.x >= 0.0f && v.x <= 1.0f) atomicAdd(&h[bin_of(v.x)], 1u);
    if (v.y >= 0.0f && v.y <= 1.0f) atomicAdd(&h[bin_of(v.y)], 1u);
    if (v.z >= 0.0f && v.z <= 1.0f) atomicAdd(&h[bin_of(v.z)], 1u);
    if (v.w >= 0.0f && v.w <= 1.0f) atomicAdd(&h[bin_of(v.w)], 1u);
}

__device__ __forceinline__ float integA(int i, int j, int tid) {
    if (i <= 0 || j <= 0) return 0.0f;
    return (float)g_cell[((size_t)((i - 1) * WW + (j - 1))) * NB + tid];
}

__device__ float region_ent(int xd, int ys, int yd, int tid) {
    float a = integA(xd, yd, tid) - integA(xd, ys, tid);
    float s = blockReduceSum(a);
    float p = a / s;
    return -blockReduceSum(p * log2f(p + 1e-9f));
}

// ------------------------- THE kernel ----------------------------------------
__global__ void __launch_bounds__(NTHR) k_mega(const float* __restrict__ x,
                                               const float* __restrict__ wfc,
                                               float* __restrict__ out) {
    __shared__ unsigned int sh[4096];   // 16KB scratch, reused across phases
    const int tid = threadIdx.x;
    const int bb  = blockIdx.x;
    const float4* __restrict__ x4 = (const float4*)x;

    // reset packed-argmax accumulator for this replay (ordered by bar0)
    if (bb == 0 && tid == 0) g_best = 0ull;

    // ===== Phase A: column-0 hists, float4 over 4 columns =====================
    // blocks 0..223: cg = bb>>4 (14 column groups), part = bb&15 (16 plane parts)
    if (bb < 224) {
        for (int i = tid; i < 4096; i += NTHR) sh[i] = 0u;   // 4 cols x 256 x 4 reps
        __syncthreads();
        int cg   = bb >> 4;
        int part = bb & 15;
        unsigned int* h = sh + (tid >> 6) * 1024;            // replica per 2 warps
        int p0 = part * 512 + tid;
        float4 a = x4[(size_t)p0 * PLANE4 + cg];
        float4 b = x4[(size_t)(p0 + 256) * PLANE4 + cg];
        if (a.x >= 0.0f && a.x <= 1.0f) atomicAdd(&h[0 * NB + bin_of(a.x)], 1u);
        if (a.y >= 0.0f && a.y <= 1.0f) atomicAdd(&h[1 * NB + bin_of(a.y)], 1u);
        if (a.z >= 0.0f && a.z <= 1.0f) atomicAdd(&h[2 * NB + bin_of(a.z)], 1u);
        if (a.w >= 0.0f && a.w <= 1.0f) atomicAdd(&h[3 * NB + bin_of(a.w)], 1u);
        if (b.x >= 0.0f && b.x <= 1.0f) atomicAdd(&h[0 * NB + bin_of(b.x)], 1u);
        if (b.y >= 0.0f && b.y <= 1.0f) atomicAdd(&h[1 * NB + bin_of(b.y)], 1u);
        if (b.z >= 0.0f && b.z <= 1.0f) atomicAdd(&h[2 * NB + bin_of(b.z)], 1u);
        if (b.w >= 0.0f && b.w <= 1.0f) atomicAdd(&h[3 * NB + bin_of(b.w)], 1u);
        __syncthreads();
        // merge 4 replicas -> global (1024 words, 4 per thread)
        #pragma unroll
        for (int k = 0; k < 4; k++) {
            int idx = tid + k * NTHR;            // col*256 + bin
            unsigned int s = sh[idx] + sh[idx + 1024] + sh[idx + 2048] + sh[idx + 3072];
            if (s) atomicAdd(&g_col0[(4 * cg + (idx >> 8)) * NB + (idx & 255)], s);
        }
    }
    gridbar(0);

    // ===== Phase B: per-column entropy + packed argmax (blocks 0..55) =========
    if (bb < WW) {
        unsigned int cu = g_col0[bb * NB + tid];
        g_col0[bb * NB + tid] = 0u;                 // ready for next replay
        float c = (float)cu;
        float s = blockReduceSum(c);
        float p = c / s;
        float ent = -blockReduceSum(p * log2f(p + 1e-9f));
        if (tid == 0) {
            unsigned long long key =
                ((unsigned long long)__float_as_uint(ent) << 8) |
                (unsigned long long)(255 - bb);     // ties -> smaller w wins
            atomicMax(&g_best, key);
        }
    }
    gridbar(1);

    // ===== every block decodes the decision locally ===========================
    unsigned long long key = *((volatile unsigned long long*)&g_best);
    int   bestw   = 255 - (int)(key & 0xFF);
    float bestEnt = __uint_as_float((unsigned)(key >> 8));
    // Bound: total_ent = -sum p*log2(p+1e-9) <= log2(256) = 8, so
    // bestEnt >= 0.9*8 => Ts0 >= 0.9 => reference loop provably never runs.
    bool need_full = !(bestEnt >= T_THRESH * 8.0f);

    int xd = 1, ys = bestw, yd = bestw + 1;   // live-path region (registers)

    // ===== Fallback (uniform branch; statistically dead on this input) ========
    if (need_full) {
        // ---- full-image histogram ----
        for (int i = tid; i < 2048; i += NTHR) sh[i] = 0u;
        __syncthreads();
        {
            unsigned int* h = sh + (tid >> 5) * NB;   // 8 replicas of 256
            const int stride = NBLK * NTHR;
            for (int i = bb * NTHR + tid; i < N4; i += stride)
                hist_one(h, x4[i]);
            __syncthreads();
            unsigned int s = 0;
            #pragma unroll
            for (int r = 0; r < 8; r++) s += sh[r * NB + tid];
            if (s) atomicAdd(&g_total[tid], s);
        }
        gridbar(2);
        // ---- ratio test on block 0 ----
        if (bb == 0) {
            float c = (float)g_total[tid];
            g_total[tid] = 0u;
            float s = blockReduceSum(c);
            float p = c / s;
            float tot = -blockReduceSum(p * log2f(p + 1e-9f));
            if (tid == 0) {
                float Ts0 = bestEnt / tot;
                if (Ts0 < T_THRESH) {
                    g_flag = 1;
                    g_total_ent = tot;
                } else {
                    g_flag = 0;
                    g_region[0] = 0; g_region[1] = 1;
                    g_region[2] = bestw; g_region[3] = bestw + 1;
                }
            }
        }
        gridbar(3);

        if (g_flag) {
            // ---- cell histograms: blocks 0..223 own (h, 14 w's) ----
            if (bb < 224) {
                for (int i = tid; i < 14 * NB; i += NTHR) sh[i] = 0u;
                __syncthreads();
                int h  = bb >> 2;
                int wq = bb & 3;
                const int TOT = BC * 14;
                for (int i = tid; i < TOT; i += NTHR) {
                    int bc   = i / 14;
                    int wloc = i % 14;
                    float v = x[(size_t)bc * PLANE + h * WW + wq * 14 + wloc];
                    if (v >= 0.0f && v <= 1.0f)
                        atomicAdd(&sh[wloc * NB + bin_of(v)], 1u);
                }
                __syncthreads();
                for (int i = tid; i < 14 * NB; i += NTHR)
                    g_cell[((size_t)(h * WW + wq * 14 + (i >> 8))) * NB + (i & 255)] = sh[i];
            }
            gridbar(4);
            // ---- 2D integral per bin (grid-stride) ----
            for (int bin = bb; bin < NB; bin += NBLK) {
                for (int i = tid; i < HH * WW; i += NTHR)
                    sh[i] = g_cell[(size_t)i * NB + bin];
                __syncthreads();
                if (tid < WW) {
                    unsigned int run = 0;
                    for (int hh = 0; hh < HH; hh++) { run += sh[hh * WW + tid]; sh[hh * WW + tid] = run; }
                }
                __syncthreads();
                if (tid < HH) {
                    unsigned int run = 0;
                    for (int w = 0; w < WW; w++) { run += sh[tid * WW + w]; sh[tid * WW + w] = run; }
                }
                __syncthreads();
                for (int i = tid; i < HH * WW; i += NTHR)
                    g_cell[(size_t)i * NB + bin] = sh[i];
                __syncthreads();
            }
            gridbar(5);
            // ---- greedy EKLM loop on block 0 ----
            if (bb == 0) {
                int fxd = 1, fys = bestw, fyd = bestw + 1;
                float total = g_total_ent;
                float Ts = region_ent(fxd, fys, fyd, tid) / total;
                bool done = false;
                for (int it = 0; it < 8192; it++) {
                    if (!(Ts < T_THRESH && !done)) break;
                    float e_cur = region_ent(fxd, fys, fyd, tid);
                    bool c1 = false, c2 = false, c3 = false;
                    if (fxd + 1 < HH)        c1 = region_ent(fxd + 1, fys, fyd, tid) > e_cur;
                    if (!c1 && fys - 1 >= 0) c2 = region_ent(fxd, fys - 1, fyd, tid) > e_cur;
                    if (!c1 && !c2 && fyd + 1 < WW)
                        c3 = region_ent(fxd, fys, fyd + 1, tid) > e_cur;
                    if (c1) fxd = fxd + 1;
                    if (c2) fys = fys - 1;
                    if (c3) fyd = fyd + 1;
                    done = !(c1 || c2 || c3);
                    Ts = region_ent(fxd, fys, fyd, tid) / total;
                }
                if (tid == 0) {
                    g_region[0] = 0; g_region[1] = fxd;
                    g_region[2] = fys; g_region[3] = fyd;
                }
            }
            gridbar(6);
        }
        // pick up fallback region
        xd = g_region[1]; ys = g_region[2]; yd = g_region[3];
    }

    // ===== Final: fused pool + GEMM, block per (b, n) =========================
    {
        int b = bb / 30;
        int n = bb % 30;
        int wlen = yd - ys;
        int cnt = xd * wlen;
        float inv = 1.0f / (float)(cnt > 0 ? cnt : 1);

        float acc = 0.0f;
        #pragma unroll
        for (int k = 0; k < 4; k++) {
            int c = tid + k * NTHR;
            const float* p = x + ((size_t)(b * CHANNELS + c)) * PLANE;
            float s = 0.0f;
            for (int i = 0; i < cnt; i++) {
                int hh = i / wlen;
                int ww2 = ys + (i - hh * wlen);
                s += p[hh * WW + ww2];
            }
            acc += s * wfc[c * 30 + n];
        }
        acc = blockReduceSum(acc);
        if (tid == 0) out[b * 30 + n] = acc * inv;
    }
}

// ------------------------- launch -------------------------------------------
extern "C" void kernel_launch(void* const* d_in, const int* in_sizes, int n_in,
                              void* d_out, int out_size) {
    const float* x   = (const float*)d_in[0];
    const float* wfc = (const float*)d_in[1];
    float* out = (float*)d_out;

    k_mega<<<NBLK, NTHR>>>(x, wfc, out);
}